// round 3
// baseline (speedup 1.0000x reference)
#include <cuda_runtime.h>
#include <cstdint>

typedef unsigned long long ull;

#define T_SEQ  1024
#define NBMAX  4
#define NTHR   64

__device__ __forceinline__ ull pk2(float lo, float hi) {
    ull r; asm("mov.b64 %0,{%1,%2};" : "=l"(r) : "f"(lo), "f"(hi)); return r;
}
__device__ __forceinline__ void upk2(ull v, float& lo, float& hi) {
    asm("mov.b64 {%0,%1},%2;" : "=f"(lo), "=f"(hi) : "l"(v));
}
__device__ __forceinline__ ull f2fma(ull a, ull b, ull c) {
    ull d; asm("fma.rn.f32x2 %0,%1,%2,%3;" : "=l"(d) : "l"(a), "l"(b), "l"(c)); return d;
}
__device__ __forceinline__ float sigf(float x) {
    float e = __expf(-x);
    return __fdividef(1.0f, 1.0f + e);
}
__device__ __forceinline__ float tanhf_fast(float x) {
    float ax = fabsf(x);
    float e  = __expf(ax + ax);
    float r  = 1.0f - __fdividef(2.0f, e + 1.0f);
    return copysignf(r, x);
}

struct __align__(16) SMem {
    float4 xbuf[2][NBMAX];        // double-buffered x_t
    float  hs[NBMAX][64];         // [0..29]=h1, [30,31]=0, [32..61]=h2, [62,63]=0
    float  act1[NBMAX][128];      // activated layer-1 gates: [gate*32 + u]
    float  act2[NBMAX][128];      // activated layer-2 gates
};

__global__ void __launch_bounds__(NTHR, 4)
lstm2_kernel(const float* __restrict__ input,
             const float* __restrict__ Wih1, const float* __restrict__ bih1,
             const float* __restrict__ Whh1, const float* __restrict__ bhh1,
             const float* __restrict__ Wih2, const float* __restrict__ bih2,
             const float* __restrict__ Whh2, const float* __restrict__ bhh2,
             const float* __restrict__ Wlin, const float* __restrict__ blin,
             float* __restrict__ out)
{
    __shared__ SMem sm;
    const int j = threadIdx.x;
    const int w = j >> 5;          // warp 0 or 1
    const int l = j & 31;
    const int lc = (l < 30) ? l : 29;

    // ---- balanced batch assignment: 592 CTAs = exactly 4/SM.
    //      SM slot s gets CTAs w'=0..3; nb pattern {4,4,3,3} (s<124, 14 batches)
    //      or {4,3,3,3} (s>=124, 13 batches). 124*14 + 24*13 = 2048.
    const int s = blockIdx.x % 148, wq = blockIdx.x / 148;
    int nb, b0;
    if (s < 124) { b0 = s * 14 + ((wq < 2) ? 4 * wq : 8 + 3 * (wq - 2)); nb = (wq < 2) ? 4 : 3; }
    else         { b0 = 1736 + (s - 124) * 13 + ((wq == 0) ? 0 : 4 + 3 * (wq - 1));
                   nb = (wq == 0) ? 4 : 3; }

    // ---- two gate rows per thread: rowA = 30w+lc (i/f), rowB = 60+30w+lc (g/o)
    const int rA = 30 * w + lc;
    const int rB = 60 + 30 * w + lc;

    ull w1xA[2], w1xB[2];     // layer1 x weights (4 floats each row)
    ull w1hA[16], w1hB[16];   // layer1 h pairs (30 + 2 zero-pad)
    ull w2A[32],  w2B[32];    // layer2: pairs over hs[0..63] (h1 | pad | h2 | pad)
    w1xA[0] = pk2(Wih1[rA * 4 + 0], Wih1[rA * 4 + 1]);
    w1xA[1] = pk2(Wih1[rA * 4 + 2], Wih1[rA * 4 + 3]);
    w1xB[0] = pk2(Wih1[rB * 4 + 0], Wih1[rB * 4 + 1]);
    w1xB[1] = pk2(Wih1[rB * 4 + 2], Wih1[rB * 4 + 3]);
#pragma unroll
    for (int p = 0; p < 16; p++) {
        w1hA[p] = (p < 15) ? pk2(Whh1[rA * 30 + 2 * p], Whh1[rA * 30 + 2 * p + 1]) : 0ull;
        w1hB[p] = (p < 15) ? pk2(Whh1[rB * 30 + 2 * p], Whh1[rB * 30 + 2 * p + 1]) : 0ull;
    }
#pragma unroll
    for (int p = 0; p < 16; p++) {
        // pairs 0..14: Wih2 over h1[0..29]; pair 15: zero pad
        w2A[p] = (p < 15) ? pk2(Wih2[rA * 30 + 2 * p], Wih2[rA * 30 + 2 * p + 1]) : 0ull;
        w2B[p] = (p < 15) ? pk2(Wih2[rB * 30 + 2 * p], Wih2[rB * 30 + 2 * p + 1]) : 0ull;
    }
#pragma unroll
    for (int p = 0; p < 16; p++) {
        // pairs 16..30: Whh2 over h2[0..29]; pair 31: zero pad
        w2A[16 + p] = (p < 15) ? pk2(Whh2[rA * 30 + 2 * p], Whh2[rA * 30 + 2 * p + 1]) : 0ull;
        w2B[16 + p] = (p < 15) ? pk2(Whh2[rB * 30 + 2 * p], Whh2[rB * 30 + 2 * p + 1]) : 0ull;
    }
    const ull bA1 = pk2(bih1[rA] + bhh1[rA], 0.0f);
    const ull bB1 = pk2(bih1[rB] + bhh1[rB], 0.0f);
    const ull bA2 = pk2(bih2[rA] + bhh2[rA], 0.0f);
    const ull bB2 = pk2(bih2[rB] + bhh2[rB], 0.0f);

    // LIN weights in registers (unit lc owned by lane l of each warp; both warps
    // hold copies — only the batch-owning warp uses them)
    float wl0 = Wlin[0 * 30 + lc], wl1 = Wlin[1 * 30 + lc];
    float wl2 = Wlin[2 * 30 + lc], wl3 = Wlin[3 * 30 + lc];
    const float bl0 = blin[0], bl1 = blin[1], bl2 = blin[2], bl3 = blin[3];

    // ---- shared init ----
    for (int idx = j; idx < NBMAX * 64; idx += NTHR) sm.hs[idx >> 6][idx & 63] = 0.0f;
    if (l >= 30) {
        int i = 2 * (l - 30) + w;      // slots 0..3
        if (i < nb)
            sm.xbuf[0][i] = *(const float4*)(input + ((size_t)(b0 + i) * T_SEQ) * 4);
    }
    __syncthreads();

    // activation/gate identities: rowA gate type = w (i or f); rowB = 2+w (g or o)
    const int gA = w, gB = 2 + w;
    // A-phase ownership: batch b -> warp (b&1), slot q=(b>>1)
    float c1s[2] = {0.0f, 0.0f};
    float c2s[2] = {0.0f, 0.0f};

    for (int t = 0; t < T_SEQ; t++) {
        const int cur = t & 1;

        // ========== G1: layer-1 gates (activated in-place) ==========
        if (l < 30) {
            for (int b = 0; b < nb; b++) {
                ulonglong2 xv = *(const ulonglong2*)&sm.xbuf[cur][b];
                ull aA = f2fma(w1xA[0], xv.x, bA1); aA = f2fma(w1xA[1], xv.y, aA);
                ull aB = f2fma(w1xB[0], xv.x, bB1); aB = f2fma(w1xB[1], xv.y, aB);
                const ulonglong2* hp = (const ulonglong2*)sm.hs[b];
#pragma unroll
                for (int p = 0; p < 8; p++) {
                    ulonglong2 h = hp[p];
                    aA = f2fma(w1hA[2 * p], h.x, aA); aA = f2fma(w1hA[2 * p + 1], h.y, aA);
                    aB = f2fma(w1hB[2 * p], h.x, aB); aB = f2fma(w1hB[2 * p + 1], h.y, aB);
                }
                float loA, hiA, loB, hiB;
                upk2(aA, loA, hiA); upk2(aB, loB, hiB);
                float gvA = loA + hiA, gvB = loB + hiB;
                gvA = sigf(gvA);                                  // i or f
                gvB = (w == 0) ? tanhf_fast(gvB) : sigf(gvB);     // g or o
                sm.act1[b][gA * 32 + l] = gvA;
                sm.act1[b][gB * 32 + l] = gvB;
            }
        } else {
            int i = 2 * (l - 30) + w, tn = t + 1;
            if (i < nb && tn < T_SEQ)
                sm.xbuf[tn & 1][i] = *(const float4*)(input + ((size_t)(b0 + i) * T_SEQ + tn) * 4);
        }
        __syncthreads();

        // ========== A1: layer-1 cell update ==========
        for (int b = w; b < nb; b += 2) {
            int q = b >> 1;
            if (l < 30) {
                float i_ = sm.act1[b][l];
                float f_ = sm.act1[b][32 + l];
                float g_ = sm.act1[b][64 + l];
                float o_ = sm.act1[b][96 + l];
                float c  = f_ * c1s[q] + i_ * g_;
                c1s[q]   = c;
                sm.hs[b][l] = o_ * tanhf_fast(c);
            }
        }
        __syncthreads();

        // ========== G2: layer-2 gates (activated in-place) ==========
        if (l < 30) {
            for (int b = 0; b < nb; b++) {
                ull aA = bA2, aB = bB2;
                const ulonglong2* hp = (const ulonglong2*)sm.hs[b];
#pragma unroll
                for (int p = 0; p < 16; p++) {
                    ulonglong2 h = hp[p];
                    aA = f2fma(w2A[2 * p], h.x, aA); aA = f2fma(w2A[2 * p + 1], h.y, aA);
                    aB = f2fma(w2B[2 * p], h.x, aB); aB = f2fma(w2B[2 * p + 1], h.y, aB);
                }
                float loA, hiA, loB, hiB;
                upk2(aA, loA, hiA); upk2(aB, loB, hiB);
                float gvA = loA + hiA, gvB = loB + hiB;
                gvA = sigf(gvA);
                gvB = (w == 0) ? tanhf_fast(gvB) : sigf(gvB);
                sm.act2[b][gA * 32 + l] = gvA;
                sm.act2[b][gB * 32 + l] = gvB;
            }
        }
        __syncthreads();

        // ========== A2: layer-2 cell update + LIN (no trailing barrier) ==========
        for (int b = w; b < nb; b += 2) {
            int q = b >> 1;
            float h2v = 0.0f;
            if (l < 30) {
                float i_ = sm.act2[b][l];
                float f_ = sm.act2[b][32 + l];
                float g_ = sm.act2[b][64 + l];
                float o_ = sm.act2[b][96 + l];
                float c  = f_ * c2s[q] + i_ * g_;
                c2s[q]   = c;
                h2v = o_ * tanhf_fast(c);
                sm.hs[b][32 + l] = h2v;
            }
            // LIN: out[b][t][d] = sum_u wlin[d][u]*h2[u] + blin[d], via butterflies
            float p0 = h2v * wl0, p1 = h2v * wl1, p2 = h2v * wl2, p3 = h2v * wl3;
#pragma unroll
            for (int m = 16; m >= 1; m >>= 1) {
                p0 += __shfl_xor_sync(0xffffffffu, p0, m);
                p1 += __shfl_xor_sync(0xffffffffu, p1, m);
                p2 += __shfl_xor_sync(0xffffffffu, p2, m);
                p3 += __shfl_xor_sync(0xffffffffu, p3, m);
            }
            if (l == 0) {
                float4 o4 = make_float4(p0 + bl0, p1 + bl1, p2 + bl2, p3 + bl3);
                *(float4*)(out + ((size_t)(b0 + b) * T_SEQ + t) * 4) = o4;
            }
        }
        // no barrier: G1(t+1) touches xbuf/hs[0..31]/act1 — all safely separated
    }
}

extern "C" void kernel_launch(void* const* d_in, const int* in_sizes, int n_in,
                              void* d_out, int out_size)
{
    const float* input = (const float*)d_in[0];
    const float* Wih1  = (const float*)d_in[1];
    const float* bih1  = (const float*)d_in[2];
    const float* Whh1  = (const float*)d_in[3];
    const float* bhh1  = (const float*)d_in[4];
    const float* Wih2  = (const float*)d_in[5];
    const float* bih2  = (const float*)d_in[6];
    const float* Whh2  = (const float*)d_in[7];
    const float* bhh2  = (const float*)d_in[8];
    const float* Wlin  = (const float*)d_in[9];
    const float* blin  = (const float*)d_in[10];
    float* out = (float*)d_out;

    lstm2_kernel<<<592, NTHR>>>(input, Wih1, bih1, Whh1, bhh1,
                                Wih2, bih2, Whh2, bhh2, Wlin, blin, out);
}

// round 4
// speedup vs baseline: 1.0220x; 1.0220x over previous
#include <cuda_runtime.h>
#include <cstdint>

typedef unsigned long long ull;

#define T_SEQ  1024
#define NBMAX  5
#define NTHR   128

__device__ __forceinline__ ull pk2(float lo, float hi) {
    ull r; asm("mov.b64 %0,{%1,%2};" : "=l"(r) : "f"(lo), "f"(hi)); return r;
}
__device__ __forceinline__ float sum2(ull v) {
    float lo, hi; asm("mov.b64 {%0,%1},%2;" : "=f"(lo), "=f"(hi) : "l"(v));
    return lo + hi;
}
__device__ __forceinline__ ull f2fma(ull a, ull b, ull c) {
    ull d; asm("fma.rn.f32x2 %0,%1,%2,%3;" : "=l"(d) : "l"(a), "l"(b), "l"(c)); return d;
}
__device__ __forceinline__ float sigf(float x) {
    float e = __expf(-x);
    return __fdividef(1.0f, 1.0f + e);
}
__device__ __forceinline__ float tanhf_fast(float x) {
    float ax = fabsf(x);
    float e  = __expf(ax + ax);
    float r  = 1.0f - __fdividef(2.0f, e + 1.0f);
    return copysignf(r, x);
}

struct __align__(16) SMem {
    float4 xbuf[2][NBMAX];     // double-buffered x_t
    float  hs[NBMAX][64];      // [0..29]=h1 (+2 pad=0), [32..61]=h2 (+2 pad=0)
    float  act1[NBMAX][120];   // activated layer-1 gates for step t+1, index=row j
    float  act2[NBMAX][120];   // activated layer-2 gates for step t
};

__global__ void __launch_bounds__(NTHR, 3)
lstm2_kernel(const float* __restrict__ input,
             const float* __restrict__ Wih1, const float* __restrict__ bih1,
             const float* __restrict__ Whh1, const float* __restrict__ bhh1,
             const float* __restrict__ Wih2, const float* __restrict__ bih2,
             const float* __restrict__ Whh2, const float* __restrict__ bhh2,
             const float* __restrict__ Wlin, const float* __restrict__ blin,
             float* __restrict__ out)
{
    __shared__ SMem sm;
    const int j  = threadIdx.x;
    const int w  = j >> 5;
    const int l  = j & 31;
    const int lc = (l < 30) ? l : 29;

    // balanced batch assignment: 444 CTAs, bids s, s+148, s+296 co-locate;
    // per-SM nb pattern {5,5,4} (s<124) or {5,4,4}. 124*14 + 24*13 = 2048.
    const int s = blockIdx.x % 148, wq = blockIdx.x / 148;
    int nb, b0;
    if (s < 124) { b0 = s * 14 + wq * 5;                                nb = (wq < 2) ? 5 : 4; }
    else         { b0 = 1736 + (s - 124) * 13 + ((wq == 0) ? 0 : 5 + (wq - 1) * 4);
                   nb = (wq == 0) ? 5 : 4; }

    // ---- row-j weights in registers (k-packed f32x2), 50 ull total ----
    const int jj = (j < 120) ? j : 119;
    ull w1x[2], w1h[16], w2a[16], w2b[16];
    w1x[0] = pk2(Wih1[jj * 4 + 0], Wih1[jj * 4 + 1]);
    w1x[1] = pk2(Wih1[jj * 4 + 2], Wih1[jj * 4 + 3]);
#pragma unroll
    for (int p = 0; p < 16; p++) {
        w1h[p] = (p < 15) ? pk2(Whh1[jj * 30 + 2 * p], Whh1[jj * 30 + 2 * p + 1]) : 0ull;
        w2a[p] = (p < 15) ? pk2(Wih2[jj * 30 + 2 * p], Wih2[jj * 30 + 2 * p + 1]) : 0ull;
        w2b[p] = (p < 15) ? pk2(Whh2[jj * 30 + 2 * p], Whh2[jj * 30 + 2 * p + 1]) : 0ull;
    }
    const ull bias1 = pk2(bih1[jj] + bhh1[jj], 0.0f);
    const ull bias2 = pk2(bih2[jj] + bhh2[jj], 0.0f);
    const bool is_tanh = (jj >= 60 && jj < 90);   // g-gate rows

    // LIN weights (unit lc) in registers
    const float wl0 = Wlin[0 * 30 + lc], wl1 = Wlin[1 * 30 + lc];
    const float wl2 = Wlin[2 * 30 + lc], wl3 = Wlin[3 * 30 + lc];
    const float bl0 = blin[0], bl1 = blin[1], bl2 = blin[2], bl3 = blin[3];

    // ---- shared init ----
    for (int idx = j; idx < NBMAX * 64; idx += NTHR) sm.hs[idx >> 6][idx & 63] = 0.0f;
    if (j >= 120) {
        int i = j - 120;
        if (i < nb) {
            sm.xbuf[0][i] = *(const float4*)(input + ((size_t)(b0 + i) * T_SEQ + 0) * 4);
            sm.xbuf[1][i] = *(const float4*)(input + ((size_t)(b0 + i) * T_SEQ + 1) * 4);
        }
    }
    __syncthreads();

    float c1s[2] = {0.0f, 0.0f};
    float c2s[2] = {0.0f, 0.0f};

    // ================= prologue: act1(0) and h1(0) =================
    if (j < 120) {
        for (int b = 0; b < nb; b++) {
            ulonglong2 xv = *(const ulonglong2*)&sm.xbuf[0][b];
            ull a1 = f2fma(w1x[0], xv.x, bias1);
            a1     = f2fma(w1x[1], xv.y, a1);
            float g1 = sum2(a1);
            sm.act1[b][j] = is_tanh ? tanhf_fast(g1) : sigf(g1);
        }
    }
    __syncthreads();
    // A1(0): warp w owns batches w, w+4
#pragma unroll
    for (int k = 0; k < 2; k++) {
        int b = w + 4 * k;
        if (b < nb && l < 30) {
            float i1 = sm.act1[b][l],      f1 = sm.act1[b][30 + l];
            float g1 = sm.act1[b][60 + l], o1 = sm.act1[b][90 + l];
            float c1 = f1 * c1s[k] + i1 * g1;
            c1s[k] = c1;
            sm.hs[b][l] = o1 * tanhf_fast(c1);
        }
    }
    __syncthreads();

    // ================= main loop: 2 barriers / step =================
    for (int t = 0; t < T_SEQ; t++) {
        // ---- P: G2(t) and G1(t+1), sharing h1(t) loads; acts fused ----
        if (j < 120) {
            const int nxt = (t + 1) & 1;
            for (int b = 0; b < nb; b++) {
                ulonglong2 xv = *(const ulonglong2*)&sm.xbuf[nxt][b];
                ull a1 = f2fma(w1x[0], xv.x, bias1);
                a1     = f2fma(w1x[1], xv.y, a1);
                ull a2 = bias2;
                const ulonglong2* hp = (const ulonglong2*)sm.hs[b];
#pragma unroll
                for (int p = 0; p < 8; p++) {          // h1(t): feeds BOTH matvecs
                    ulonglong2 h = hp[p];
                    a1 = f2fma(w1h[2 * p], h.x, a1); a1 = f2fma(w1h[2 * p + 1], h.y, a1);
                    a2 = f2fma(w2a[2 * p], h.x, a2); a2 = f2fma(w2a[2 * p + 1], h.y, a2);
                }
#pragma unroll
                for (int p = 0; p < 8; p++) {          // h2(t-1)
                    ulonglong2 h = hp[8 + p];
                    a2 = f2fma(w2b[2 * p], h.x, a2); a2 = f2fma(w2b[2 * p + 1], h.y, a2);
                }
                float g1 = sum2(a1), g2 = sum2(a2);
                sm.act1[b][j] = is_tanh ? tanhf_fast(g1) : sigf(g1);
                sm.act2[b][j] = is_tanh ? tanhf_fast(g2) : sigf(g2);
            }
        } else {
            int i = j - 120, tn = t + 2;
            if (i < nb && tn < T_SEQ)
                sm.xbuf[tn & 1][i] = *(const float4*)(input + ((size_t)(b0 + i) * T_SEQ + tn) * 4);
        }
        __syncthreads();

        // ---- A: A2(t) -> h2(t) + LIN(t); A1(t+1) -> h1(t+1) ----
#pragma unroll
        for (int k = 0; k < 2; k++) {
            int b = w + 4 * k;
            if (b < nb) {
                float h2v = 0.0f;
                if (l < 30) {
                    float i2 = sm.act2[b][l],      f2 = sm.act2[b][30 + l];
                    float g2 = sm.act2[b][60 + l], o2 = sm.act2[b][90 + l];
                    float c2 = f2 * c2s[k] + i2 * g2;
                    c2s[k] = c2;
                    h2v = o2 * tanhf_fast(c2);
                    sm.hs[b][32 + l] = h2v;

                    float i1 = sm.act1[b][l],      f1 = sm.act1[b][30 + l];
                    float g1 = sm.act1[b][60 + l], o1 = sm.act1[b][90 + l];
                    float c1 = f1 * c1s[k] + i1 * g1;
                    c1s[k] = c1;
                    sm.hs[b][l] = o1 * tanhf_fast(c1);
                }
                // LIN(t) via warp butterfly (lanes >=30 contribute h2v=0)
                float p0 = h2v * wl0, p1 = h2v * wl1, p2 = h2v * wl2, p3 = h2v * wl3;
#pragma unroll
                for (int m = 16; m >= 1; m >>= 1) {
                    p0 += __shfl_xor_sync(0xffffffffu, p0, m);
                    p1 += __shfl_xor_sync(0xffffffffu, p1, m);
                    p2 += __shfl_xor_sync(0xffffffffu, p2, m);
                    p3 += __shfl_xor_sync(0xffffffffu, p3, m);
                }
                if (l == 0) {
                    float4 o4 = make_float4(p0 + bl0, p1 + bl1, p2 + bl2, p3 + bl3);
                    *(float4*)(out + ((size_t)(b0 + b) * T_SEQ + t) * 4) = o4;
                }
            }
        }
        __syncthreads();
        // note: at t = T_SEQ-1, act1/h1 for step T_SEQ are computed from stale x
        // and never consumed — harmless finite garbage.
    }
}

extern "C" void kernel_launch(void* const* d_in, const int* in_sizes, int n_in,
                              void* d_out, int out_size)
{
    const float* input = (const float*)d_in[0];
    const float* Wih1  = (const float*)d_in[1];
    const float* bih1  = (const float*)d_in[2];
    const float* Whh1  = (const float*)d_in[3];
    const float* bhh1  = (const float*)d_in[4];
    const float* Wih2  = (const float*)d_in[5];
    const float* bih2  = (const float*)d_in[6];
    const float* Whh2  = (const float*)d_in[7];
    const float* bhh2  = (const float*)d_in[8];
    const float* Wlin  = (const float*)d_in[9];
    const float* blin  = (const float*)d_in[10];
    float* out = (float*)d_out;

    lstm2_kernel<<<444, NTHR>>>(input, Wih1, bih1, Whh1, bhh1,
                                Wih2, bih2, Whh2, bhh2, Wlin, blin, out);
}

// round 5
// speedup vs baseline: 1.0893x; 1.0658x over previous
#include <cuda_runtime.h>
#include <cstdint>

typedef unsigned long long ull;

#define T_SEQ  1024
#define NTHR   128

__device__ __forceinline__ ull pk2(float lo, float hi) {
    ull r; asm("mov.b64 %0,{%1,%2};" : "=l"(r) : "f"(lo), "f"(hi)); return r;
}
__device__ __forceinline__ float sum2(ull v) {
    float lo, hi; asm("mov.b64 {%0,%1},%2;" : "=f"(lo), "=f"(hi) : "l"(v));
    return lo + hi;
}
__device__ __forceinline__ ull f2fma(ull a, ull b, ull c) {
    ull d; asm("fma.rn.f32x2 %0,%1,%2,%3;" : "=l"(d) : "l"(a), "l"(b), "l"(c)); return d;
}
__device__ __forceinline__ ull f2add(ull a, ull b) {
    ull d; asm("add.rn.f32x2 %0,%1,%2;" : "=l"(d) : "l"(a), "l"(b)); return d;
}
__device__ __forceinline__ float sigf(float x) {
    float e = __expf(-x);
    return __fdividef(1.0f, 1.0f + e);
}
__device__ __forceinline__ float tanhf_fast(float x) {
    float ax = fabsf(x);
    float e  = __expf(ax + ax);
    float r  = 1.0f - __fdividef(2.0f, e + 1.0f);
    return copysignf(r, x);
}

struct __align__(16) SMem {
    float4 xbuf[2][5];      // double-buffered x_t
    float  hs[5][64];       // [0..29]=h1 (+2 pad=0), [32..61]=h2 (+2 pad=0)
    float  act1[5][120];    // activated layer-1 gates for step t+1
    float  act2[5][120];    // activated layer-2 gates for step t
};

template<int NB>
__device__ __forceinline__ void run_body(
    const float* __restrict__ input,
    const float* __restrict__ Wih1, const float* __restrict__ bih1,
    const float* __restrict__ Whh1, const float* __restrict__ bhh1,
    const float* __restrict__ Wih2, const float* __restrict__ bih2,
    const float* __restrict__ Whh2, const float* __restrict__ bhh2,
    const float* __restrict__ Wlin, const float* __restrict__ blin,
    float* __restrict__ out, SMem& sm, int b0)
{
    const int j  = threadIdx.x;
    const int w  = j >> 5;
    const int l  = j & 31;
    const int lc = (l < 30) ? l : 29;

    // ---- row-j weights in registers (15 real k-pairs, no zero pads) ----
    const int jj = (j < 120) ? j : 119;
    ull w1x[2], w1h[15], w2a[15], w2b[15];
    w1x[0] = pk2(Wih1[jj * 4 + 0], Wih1[jj * 4 + 1]);
    w1x[1] = pk2(Wih1[jj * 4 + 2], Wih1[jj * 4 + 3]);
#pragma unroll
    for (int p = 0; p < 15; p++) {
        w1h[p] = pk2(Whh1[jj * 30 + 2 * p], Whh1[jj * 30 + 2 * p + 1]);
        w2a[p] = pk2(Wih2[jj * 30 + 2 * p], Wih2[jj * 30 + 2 * p + 1]);
        w2b[p] = pk2(Whh2[jj * 30 + 2 * p], Whh2[jj * 30 + 2 * p + 1]);
    }
    const ull bias1 = pk2(bih1[jj] + bhh1[jj], 0.0f);
    const ull bias2 = pk2(bih2[jj] + bhh2[jj], 0.0f);
    const bool is_tanh = (jj >= 60 && jj < 90);

    const float wl0 = Wlin[0 * 30 + lc], wl1 = Wlin[1 * 30 + lc];
    const float wl2 = Wlin[2 * 30 + lc], wl3 = Wlin[3 * 30 + lc];
    const float bl0 = blin[0], bl1 = blin[1], bl2 = blin[2], bl3 = blin[3];

    // ---- shared init ----
    for (int idx = j; idx < 5 * 64; idx += NTHR) sm.hs[idx >> 6][idx & 63] = 0.0f;
    if (j >= 120) {
        int i = j - 120;
        if (i < NB) {
            sm.xbuf[0][i] = *(const float4*)(input + ((size_t)(b0 + i) * T_SEQ + 0) * 4);
            sm.xbuf[1][i] = *(const float4*)(input + ((size_t)(b0 + i) * T_SEQ + 1) * 4);
        }
    }
    __syncthreads();

    float c1s[2] = {0.0f, 0.0f};
    float c2s[2] = {0.0f, 0.0f};

    // ---- prologue: act1(0), h1(0) ----
    if (j < 120) {
#pragma unroll
        for (int b = 0; b < NB; b++) {
            ulonglong2 xv = *(const ulonglong2*)&sm.xbuf[0][b];
            ull a1 = f2fma(w1x[0], xv.x, bias1);
            a1     = f2fma(w1x[1], xv.y, a1);
            float g1 = sum2(a1);
            sm.act1[b][j] = is_tanh ? tanhf_fast(g1) : sigf(g1);
        }
    }
    __syncthreads();
#pragma unroll
    for (int k = 0; k < 2; k++) {
        int b = w + 4 * k;
        if (b < NB && l < 30) {
            float i1 = sm.act1[b][l],      f1 = sm.act1[b][30 + l];
            float g1 = sm.act1[b][60 + l], o1 = sm.act1[b][90 + l];
            float c1 = f1 * c1s[k] + i1 * g1;
            c1s[k] = c1;
            sm.hs[b][l] = o1 * tanhf_fast(c1);
        }
    }
    __syncthreads();

    // ---- main loop: 2 barriers/step ----
#pragma unroll 1
    for (int t = 0; t < T_SEQ; t++) {
        const int nxt = (t + 1) & 1;

        // P: G2(t) + G1(t+1), sharing h1(t); activations fused; fully unrolled
        if (j < 120) {
#pragma unroll
            for (int b = 0; b < NB; b++) {
                const ulonglong2* hp = (const ulonglong2*)sm.hs[b];
                ulonglong2 H[8], K[8];
#pragma unroll
                for (int p = 0; p < 8; p++) { H[p] = hp[p]; K[p] = hp[8 + p]; }
                ulonglong2 xv = *(const ulonglong2*)&sm.xbuf[nxt][b];

                // 4 independent chains: a1a(10), a1b(7), a2a(15), a2b(15)
                ull a1a = f2fma(w1x[0], xv.x, bias1);
                a1a     = f2fma(w1x[1], xv.y, a1a);
                ull a1b = 0, a2a = bias2, a2b = 0;
#pragma unroll
                for (int p = 0; p < 7; p++) {
                    a1a = f2fma(w1h[2 * p],     H[p].x, a1a);
                    a1b = f2fma(w1h[2 * p + 1], H[p].y, a1b);
                    a2a = f2fma(w2a[2 * p],     H[p].x, a2a);
                    a2a = f2fma(w2a[2 * p + 1], H[p].y, a2a);
                    a2b = f2fma(w2b[2 * p],     K[p].x, a2b);
                    a2b = f2fma(w2b[2 * p + 1], K[p].y, a2b);
                }
                a1a = f2fma(w1h[14], H[7].x, a1a);   // pair 14 (floats 28,29)
                a2a = f2fma(w2a[14], H[7].x, a2a);
                a2b = f2fma(w2b[14], K[7].x, a2b);

                float g1 = sum2(f2add(a1a, a1b));
                float g2 = sum2(f2add(a2a, a2b));
                sm.act1[b][j] = is_tanh ? tanhf_fast(g1) : sigf(g1);
                sm.act2[b][j] = is_tanh ? tanhf_fast(g2) : sigf(g2);
            }
        } else {
            int i = j - 120, tn = t + 2;
            if (i < NB && tn < T_SEQ)
                sm.xbuf[tn & 1][i] = *(const float4*)(input + ((size_t)(b0 + i) * T_SEQ + tn) * 4);
        }
        __syncthreads();

        // A: A2(t) -> h2(t) + LIN(t); A1(t+1) -> h1(t+1)
#pragma unroll
        for (int k = 0; k < 2; k++) {
            int b = w + 4 * k;
            if (b < NB) {
                float h2v = 0.0f;
                if (l < 30) {
                    float i2 = sm.act2[b][l],      f2 = sm.act2[b][30 + l];
                    float g2 = sm.act2[b][60 + l], o2 = sm.act2[b][90 + l];
                    float c2 = f2 * c2s[k] + i2 * g2;
                    c2s[k] = c2;
                    h2v = o2 * tanhf_fast(c2);
                    sm.hs[b][32 + l] = h2v;

                    float i1 = sm.act1[b][l],      f1 = sm.act1[b][30 + l];
                    float g1 = sm.act1[b][60 + l], o1 = sm.act1[b][90 + l];
                    float c1 = f1 * c1s[k] + i1 * g1;
                    c1s[k] = c1;
                    sm.hs[b][l] = o1 * tanhf_fast(c1);
                }
                float p0 = h2v * wl0, p1 = h2v * wl1, p2 = h2v * wl2, p3 = h2v * wl3;
#pragma unroll
                for (int m = 16; m >= 1; m >>= 1) {
                    p0 += __shfl_xor_sync(0xffffffffu, p0, m);
                    p1 += __shfl_xor_sync(0xffffffffu, p1, m);
                    p2 += __shfl_xor_sync(0xffffffffu, p2, m);
                    p3 += __shfl_xor_sync(0xffffffffu, p3, m);
                }
                if (l == 0) {
                    float4 o4 = make_float4(p0 + bl0, p1 + bl1, p2 + bl2, p3 + bl3);
                    *(float4*)(out + ((size_t)(b0 + b) * T_SEQ + t) * 4) = o4;
                }
            }
        }
        __syncthreads();
    }
}

__global__ void __launch_bounds__(NTHR, 3)
lstm2_kernel(const float* __restrict__ input,
             const float* __restrict__ Wih1, const float* __restrict__ bih1,
             const float* __restrict__ Whh1, const float* __restrict__ bhh1,
             const float* __restrict__ Wih2, const float* __restrict__ bih2,
             const float* __restrict__ Whh2, const float* __restrict__ bhh2,
             const float* __restrict__ Wlin, const float* __restrict__ blin,
             float* __restrict__ out)
{
    __shared__ SMem sm;
    // balanced batch map: 444 CTAs; bids s, s+148, s+296 co-locate on one SM;
    // per-SM nb pattern {5,5,4} (s<124, 14 batches) or {5,4,4} (13). Sum = 2048.
    const int s = blockIdx.x % 148, wq = blockIdx.x / 148;
    int nb, b0;
    if (s < 124) { b0 = s * 14 + wq * 5;                                nb = (wq < 2) ? 5 : 4; }
    else         { b0 = 1736 + (s - 124) * 13 + ((wq == 0) ? 0 : 5 + (wq - 1) * 4);
                   nb = (wq == 0) ? 5 : 4; }

    if (nb == 5)
        run_body<5>(input, Wih1, bih1, Whh1, bhh1, Wih2, bih2, Whh2, bhh2,
                    Wlin, blin, out, sm, b0);
    else
        run_body<4>(input, Wih1, bih1, Whh1, bhh1, Wih2, bih2, Whh2, bhh2,
                    Wlin, blin, out, sm, b0);
}

extern "C" void kernel_launch(void* const* d_in, const int* in_sizes, int n_in,
                              void* d_out, int out_size)
{
    const float* input = (const float*)d_in[0];
    const float* Wih1  = (const float*)d_in[1];
    const float* bih1  = (const float*)d_in[2];
    const float* Whh1  = (const float*)d_in[3];
    const float* bhh1  = (const float*)d_in[4];
    const float* Wih2  = (const float*)d_in[5];
    const float* bih2  = (const float*)d_in[6];
    const float* Whh2  = (const float*)d_in[7];
    const float* bhh2  = (const float*)d_in[8];
    const float* Wlin  = (const float*)d_in[9];
    const float* blin  = (const float*)d_in[10];
    float* out = (float*)d_out;

    lstm2_kernel<<<444, NTHR>>>(input, Wih1, bih1, Whh1, bhh1,
                                Wih2, bih2, Whh2, bhh2, Wlin, blin, out);
}

// round 6
// speedup vs baseline: 1.1422x; 1.0485x over previous
#include <cuda_runtime.h>
#include <cstdint>

typedef unsigned long long ull;

#define T_SEQ  1024
#define NTHR   256

__device__ __forceinline__ ull pk2(float lo, float hi) {
    ull r; asm("mov.b64 %0,{%1,%2};" : "=l"(r) : "f"(lo), "f"(hi)); return r;
}
__device__ __forceinline__ float sum2(ull v) {
    float lo, hi; asm("mov.b64 {%0,%1},%2;" : "=f"(lo), "=f"(hi) : "l"(v));
    return lo + hi;
}
__device__ __forceinline__ ull f2fma(ull a, ull b, ull c) {
    ull d; asm("fma.rn.f32x2 %0,%1,%2,%3;" : "=l"(d) : "l"(a), "l"(b), "l"(c)); return d;
}
__device__ __forceinline__ ull f2add(ull a, ull b) {
    ull d; asm("add.rn.f32x2 %0,%1,%2;" : "=l"(d) : "l"(a), "l"(b)); return d;
}
__device__ __forceinline__ float sigf(float x) {
    float e = __expf(-x);
    return __fdividef(1.0f, 1.0f + e);
}
__device__ __forceinline__ float tanhf_fast(float x) {
    float ax = fabsf(x);
    float e  = __expf(ax + ax);
    float r  = 1.0f - __fdividef(2.0f, e + 1.0f);
    return copysignf(r, x);
}

struct __align__(16) SMem {
    float4 xbuf[2][7];       // double-buffered x_t
    float  hs[7][64];        // [0..29]=h1(+2 pad), [32..61]=h2(+2 pad)
    float  part1[7][120];    // B's layer-1 partial sums (k-high)
    float  part2[7][120];    // A's layer-2 partial sums (k-low)
    float  act1[7][120];     // activated layer-1 gates, step t+1
    float  act2[7][120];     // activated layer-2 gates, step t
};

template<int NB>
__device__ __forceinline__ void run_body(
    const float* __restrict__ input,
    const float* __restrict__ Wih1, const float* __restrict__ bih1,
    const float* __restrict__ Whh1, const float* __restrict__ bhh1,
    const float* __restrict__ Wih2, const float* __restrict__ bih2,
    const float* __restrict__ Whh2, const float* __restrict__ bhh2,
    const float* __restrict__ Wlin, const float* __restrict__ blin,
    float* __restrict__ out, SMem& sm, int b0)
{
    const int tid = threadIdx.x;
    const int wid = tid >> 5;
    const int l   = tid & 31;
    const int lc  = (l < 30) ? l : 29;

    const bool isA = (tid < 120);                 // k in [0,16)  of row j
    const bool isB = (tid >= 128 && tid < 248);   // k in [16,30) of row j
    const int  j   = isA ? tid : (isB ? tid - 128 : 0);
    const bool is_tanh = (j >= 60 && j < 90);

    // ---- role-dependent weights in one register array (26 ull max) ----
    // A: [0,1]=Wih1 x-pairs; [2..9]=Whh1 p0-7; [10..17]=Wih2 p0-7; [18..25]=Whh2 p0-7
    // B: [2..8]=Whh1 p8-14;  [10..16]=Wih2 p8-14; [18..24]=Whh2 p8-14
    ull wreg[26];
#pragma unroll
    for (int p = 0; p < 26; p++) wreg[p] = 0ull;
    ull bias1 = 0, bias2 = 0;
    if (isA) {
        wreg[0] = pk2(Wih1[j * 4 + 0], Wih1[j * 4 + 1]);
        wreg[1] = pk2(Wih1[j * 4 + 2], Wih1[j * 4 + 3]);
#pragma unroll
        for (int p = 0; p < 8; p++) {
            wreg[2 + p]  = pk2(Whh1[j * 30 + 2 * p], Whh1[j * 30 + 2 * p + 1]);
            wreg[10 + p] = pk2(Wih2[j * 30 + 2 * p], Wih2[j * 30 + 2 * p + 1]);
            wreg[18 + p] = pk2(Whh2[j * 30 + 2 * p], Whh2[j * 30 + 2 * p + 1]);
        }
        bias1 = pk2(bih1[j] + bhh1[j], 0.0f);
        bias2 = pk2(bih2[j] + bhh2[j], 0.0f);
    } else if (isB) {
#pragma unroll
        for (int p = 0; p < 7; p++) {
            wreg[2 + p]  = pk2(Whh1[j * 30 + 16 + 2 * p], Whh1[j * 30 + 17 + 2 * p]);
            wreg[10 + p] = pk2(Wih2[j * 30 + 16 + 2 * p], Wih2[j * 30 + 17 + 2 * p]);
            wreg[18 + p] = pk2(Whh2[j * 30 + 16 + 2 * p], Whh2[j * 30 + 17 + 2 * p]);
        }
    }

    const float wl0 = Wlin[0 * 30 + lc], wl1 = Wlin[1 * 30 + lc];
    const float wl2 = Wlin[2 * 30 + lc], wl3 = Wlin[3 * 30 + lc];
    const float bl0 = blin[0], bl1 = blin[1], bl2 = blin[2], bl3 = blin[3];

    // ---- shared init ----
    for (int idx = tid; idx < 7 * 64; idx += NTHR) sm.hs[idx >> 6][idx & 63] = 0.0f;
    if (tid >= 248) {
        int i = tid - 248;
        if (i < NB) {
            sm.xbuf[0][i] = *(const float4*)(input + ((size_t)(b0 + i) * T_SEQ + 0) * 4);
            sm.xbuf[1][i] = *(const float4*)(input + ((size_t)(b0 + i) * T_SEQ + 1) * 4);
        }
    }
    __syncthreads();

    float keep[NB];    // A: a1 partial per batch; B: b2 partial per batch
    float c1 = 0.0f, c2 = 0.0f;   // warp wid owns batch wid, lane l = unit

    // ---- prologue: act1(0) = act(Wih1 x(0) + b) since h1(-1)=0 ----
    if (isA) {
#pragma unroll
        for (int b = 0; b < NB; b++) {
            ulonglong2 xv = *(const ulonglong2*)&sm.xbuf[0][b];
            float v = sum2(f2fma(wreg[1], xv.y, f2fma(wreg[0], xv.x, bias1)));
            sm.act1[b][j] = is_tanh ? tanhf_fast(v) : sigf(v);
        }
    }
    __syncthreads();
    if (wid < NB && l < 30) {
        float i1 = sm.act1[wid][l],      f1 = sm.act1[wid][30 + l];
        float g1 = sm.act1[wid][60 + l], o1 = sm.act1[wid][90 + l];
        c1 = f1 * 0.0f + i1 * g1;
        sm.hs[wid][l] = o1 * tanhf_fast(c1);
    }
    __syncthreads();

    // ================= main loop: 3 barriers/step =================
#pragma unroll 1
    for (int t = 0; t < T_SEQ; t++) {
        const int nxt = (t + 1) & 1;

        // ---- P: partial sums for G1(t+1) and G2(t), k-split A/B ----
        if (isA) {
#pragma unroll
            for (int b = 0; b < NB; b++) {
                const ulonglong2* hp = (const ulonglong2*)sm.hs[b];
                ulonglong2 xv = *(const ulonglong2*)&sm.xbuf[nxt][b];
                ulonglong2 h0 = hp[0], h1v = hp[1], h2v = hp[2], h3v = hp[3];
                ulonglong2 g0 = hp[8], g1v = hp[9], g2v = hp[10], g3v = hp[11];

                ull a1 = f2fma(wreg[0], xv.x, bias1);
                a1     = f2fma(wreg[1], xv.y, a1);
                a1 = f2fma(wreg[2], h0.x, a1);  a1 = f2fma(wreg[3], h0.y, a1);
                a1 = f2fma(wreg[4], h1v.x, a1); a1 = f2fma(wreg[5], h1v.y, a1);
                a1 = f2fma(wreg[6], h2v.x, a1); a1 = f2fma(wreg[7], h2v.y, a1);
                a1 = f2fma(wreg[8], h3v.x, a1); a1 = f2fma(wreg[9], h3v.y, a1);

                ull a2a = f2fma(wreg[10], h0.x, bias2);
                a2a = f2fma(wreg[11], h0.y, a2a);
                a2a = f2fma(wreg[12], h1v.x, a2a); a2a = f2fma(wreg[13], h1v.y, a2a);
                a2a = f2fma(wreg[14], h2v.x, a2a); a2a = f2fma(wreg[15], h2v.y, a2a);
                a2a = f2fma(wreg[16], h3v.x, a2a); a2a = f2fma(wreg[17], h3v.y, a2a);

                ull a2b = 0;
                a2b = f2fma(wreg[18], g0.x, a2b);  a2b = f2fma(wreg[19], g0.y, a2b);
                a2b = f2fma(wreg[20], g1v.x, a2b); a2b = f2fma(wreg[21], g1v.y, a2b);
                a2b = f2fma(wreg[22], g2v.x, a2b); a2b = f2fma(wreg[23], g2v.y, a2b);
                a2b = f2fma(wreg[24], g3v.x, a2b); a2b = f2fma(wreg[25], g3v.y, a2b);

                keep[b] = sum2(a1);
                sm.part2[b][j] = sum2(f2add(a2a, a2b));
            }
        } else if (isB) {
#pragma unroll
            for (int b = 0; b < NB; b++) {
                const ulonglong2* hp = (const ulonglong2*)sm.hs[b];
                ulonglong2 h4 = hp[4],  h5 = hp[5],  h6 = hp[6],  h7 = hp[7];
                ulonglong2 g4 = hp[12], g5 = hp[13], g6 = hp[14], g7 = hp[15];

                ull b1 = 0;
                b1 = f2fma(wreg[2], h4.x, b1); b1 = f2fma(wreg[3], h4.y, b1);
                b1 = f2fma(wreg[4], h5.x, b1); b1 = f2fma(wreg[5], h5.y, b1);
                b1 = f2fma(wreg[6], h6.x, b1); b1 = f2fma(wreg[7], h6.y, b1);
                b1 = f2fma(wreg[8], h7.x, b1);

                ull b2a = 0;
                b2a = f2fma(wreg[10], h4.x, b2a); b2a = f2fma(wreg[11], h4.y, b2a);
                b2a = f2fma(wreg[12], h5.x, b2a); b2a = f2fma(wreg[13], h5.y, b2a);
                b2a = f2fma(wreg[14], h6.x, b2a); b2a = f2fma(wreg[15], h6.y, b2a);
                b2a = f2fma(wreg[16], h7.x, b2a);

                ull b2b = 0;
                b2b = f2fma(wreg[18], g4.x, b2b); b2b = f2fma(wreg[19], g4.y, b2b);
                b2b = f2fma(wreg[20], g5.x, b2b); b2b = f2fma(wreg[21], g5.y, b2b);
                b2b = f2fma(wreg[22], g6.x, b2b); b2b = f2fma(wreg[23], g6.y, b2b);
                b2b = f2fma(wreg[24], g7.x, b2b);

                sm.part1[b][j] = sum2(b1);
                keep[b] = sum2(f2add(b2a, b2b));
            }
        } else if (tid >= 248) {
            int i = tid - 248, tn = t + 2;
            if (i < NB && tn < T_SEQ)
                sm.xbuf[tn & 1][i] = *(const float4*)(input + ((size_t)(b0 + i) * T_SEQ + tn) * 4);
        }
        __syncthreads();

        // ---- C: combine partials + activations (A -> act1, B -> act2) ----
        if (isA) {
#pragma unroll
            for (int b = 0; b < NB; b++) {
                float v = keep[b] + sm.part1[b][j];
                sm.act1[b][j] = is_tanh ? tanhf_fast(v) : sigf(v);
            }
        } else if (isB) {
#pragma unroll
            for (int b = 0; b < NB; b++) {
                float v = keep[b] + sm.part2[b][j];
                sm.act2[b][j] = is_tanh ? tanhf_fast(v) : sigf(v);
            }
        }
        __syncthreads();

        // ---- A: cell updates (warp wid owns batch wid) + LIN(t) ----
        if (wid < NB) {
            const int b = wid;
            float h2o = 0.0f;
            if (l < 30) {
                float i2 = sm.act2[b][l],      f2 = sm.act2[b][30 + l];
                float g2 = sm.act2[b][60 + l], o2 = sm.act2[b][90 + l];
                c2 = f2 * c2 + i2 * g2;
                h2o = o2 * tanhf_fast(c2);
                sm.hs[b][32 + l] = h2o;

                float i1 = sm.act1[b][l],      f1 = sm.act1[b][30 + l];
                float g1 = sm.act1[b][60 + l], o1 = sm.act1[b][90 + l];
                c1 = f1 * c1 + i1 * g1;
                sm.hs[b][l] = o1 * tanhf_fast(c1);
            }
            float p0 = h2o * wl0, p1 = h2o * wl1, p2 = h2o * wl2, p3 = h2o * wl3;
#pragma unroll
            for (int m = 16; m >= 1; m >>= 1) {
                p0 += __shfl_xor_sync(0xffffffffu, p0, m);
                p1 += __shfl_xor_sync(0xffffffffu, p1, m);
                p2 += __shfl_xor_sync(0xffffffffu, p2, m);
                p3 += __shfl_xor_sync(0xffffffffu, p3, m);
            }
            if (l == 0) {
                float4 o4 = make_float4(p0 + bl0, p1 + bl1, p2 + bl2, p3 + bl3);
                *(float4*)(out + ((size_t)(b0 + b) * T_SEQ + t) * 4) = o4;
            }
        }
        __syncthreads();
        // final iteration computes act1/h1 for step T_SEQ from stale x —
        // finite values, never consumed.
    }
}

__global__ void __launch_bounds__(NTHR, 2)
lstm2_kernel(const float* __restrict__ input,
             const float* __restrict__ Wih1, const float* __restrict__ bih1,
             const float* __restrict__ Whh1, const float* __restrict__ bhh1,
             const float* __restrict__ Wih2, const float* __restrict__ bih2,
             const float* __restrict__ Whh2, const float* __restrict__ bhh2,
             const float* __restrict__ Wlin, const float* __restrict__ blin,
             float* __restrict__ out)
{
    __shared__ SMem sm;
    // 296 CTAs = 2/SM; bids s and s+148 co-locate. Per-SM nb {7,7} (s<124)
    // or {7,6}: 124*14 + 24*13 = 2048.
    const int s = blockIdx.x % 148, wq = blockIdx.x / 148;
    int nb, b0;
    if (s < 124) { b0 = s * 14 + wq * 7;                    nb = 7; }
    else         { b0 = 1736 + (s - 124) * 13 + wq * 7;     nb = (wq == 0) ? 7 : 6; }

    if (nb == 7)
        run_body<7>(input, Wih1, bih1, Whh1, bhh1, Wih2, bih2, Whh2, bhh2,
                    Wlin, blin, out, sm, b0);
    else
        run_body<6>(input, Wih1, bih1, Whh1, bhh1, Wih2, bih2, Whh2, bhh2,
                    Wlin, blin, out, sm, b0);
}

extern "C" void kernel_launch(void* const* d_in, const int* in_sizes, int n_in,
                              void* d_out, int out_size)
{
    const float* input = (const float*)d_in[0];
    const float* Wih1  = (const float*)d_in[1];
    const float* bih1  = (const float*)d_in[2];
    const float* Whh1  = (const float*)d_in[3];
    const float* bhh1  = (const float*)d_in[4];
    const float* Wih2  = (const float*)d_in[5];
    const float* bih2  = (const float*)d_in[6];
    const float* Whh2  = (const float*)d_in[7];
    const float* bhh2  = (const float*)d_in[8];
    const float* Wlin  = (const float*)d_in[9];
    const float* blin  = (const float*)d_in[10];
    float* out = (float*)d_out;

    lstm2_kernel<<<296, NTHR>>>(input, Wih1, bih1, Whh1, bhh1,
                                Wih2, bih2, Whh2, bhh2, Wlin, blin, out);
}

// round 7
// speedup vs baseline: 1.2770x; 1.1180x over previous
#include <cuda_runtime.h>
#include <cstdint>

typedef unsigned long long ull;

#define T_SEQ  1024
#define NTHR   256

__device__ __forceinline__ ull pk2(float lo, float hi) {
    ull r; asm("mov.b64 %0,{%1,%2};" : "=l"(r) : "f"(lo), "f"(hi)); return r;
}
__device__ __forceinline__ float sum2(ull v) {
    float lo, hi; asm("mov.b64 {%0,%1},%2;" : "=f"(lo), "=f"(hi) : "l"(v));
    return lo + hi;
}
__device__ __forceinline__ ull f2fma(ull a, ull b, ull c) {
    ull d; asm("fma.rn.f32x2 %0,%1,%2,%3;" : "=l"(d) : "l"(a), "l"(b), "l"(c)); return d;
}
__device__ __forceinline__ ull f2add(ull a, ull b) {
    ull d; asm("add.rn.f32x2 %0,%1,%2;" : "=l"(d) : "l"(a), "l"(b)); return d;
}
__device__ __forceinline__ float tanhf_fast(float x) {
    float ax = fabsf(x);
    float e  = __expf(ax + ax);
    float r  = 1.0f - __fdividef(2.0f, e + 1.0f);
    return copysignf(r, x);
}
// unified gate activation: s=1 -> sigmoid, s=2 -> tanh
__device__ __forceinline__ float act_unified(float v, float s) {
    float e = __expf(-s * v);
    return __fdividef(s, 1.0f + e) - (s - 1.0f);
}

struct __align__(16) SMem {
    float4 xbuf[2][7];       // double-buffered x_t
    float  hs[7][64];        // [0..29]=h1(+2 pad=0), [32..61]=h2(+2 pad=0)
    float  act1[7][120];     // interleaved: [u*4+g], layer-1 gates for step t+1
    float  act2[7][120];     // interleaved: [u*4+g], layer-2 gates for step t
};

template<int NB>
__device__ __forceinline__ void run_body(
    const float* __restrict__ input,
    const float* __restrict__ Wih1, const float* __restrict__ bih1,
    const float* __restrict__ Whh1, const float* __restrict__ bhh1,
    const float* __restrict__ Wih2, const float* __restrict__ bih2,
    const float* __restrict__ Whh2, const float* __restrict__ bhh2,
    const float* __restrict__ Wlin, const float* __restrict__ blin,
    float* __restrict__ out, SMem& sm, int b0)
{
    const int tid  = threadIdx.x;
    const int w    = tid >> 5;
    const int l    = tid & 31;
    const int r    = l & 15;          // row index within warp (valid < 15)
    const int half = l >> 4;          // 0: k in [0,16), 1: k in [16,30)
    const int lc   = (l < 30) ? l : 29;

    const int  jraw = w * 15 + r;
    const int  j    = (jraw < 120) ? jraw : 119;   // clamp (lane r==15, w==7)
    const int  g    = j / 30, u = j % 30;
    const bool valid = (r < 15);
    const float sgate = (g == 2) ? 2.0f : 1.0f;    // tanh for g-gate else sigmoid

    // ---- k-split weights, uniform register layout (26 ull) ----
    // wx: x weights (half 0 only, else 0); wh/wa/wb: 8 k-pairs of the half's slice
    const int k0 = half * 16;
    ull wx0 = 0, wx1 = 0, wh[8], wa[8], wb[8], bias1 = 0, bias2 = 0;
    if (half == 0) {
        wx0 = pk2(Wih1[j * 4 + 0], Wih1[j * 4 + 1]);
        wx1 = pk2(Wih1[j * 4 + 2], Wih1[j * 4 + 3]);
        bias1 = pk2(bih1[j] + bhh1[j], 0.0f);
        bias2 = pk2(bih2[j] + bhh2[j], 0.0f);
    }
#pragma unroll
    for (int p = 0; p < 8; p++) {
        int k = k0 + 2 * p;
        bool ok = (k + 1 < 30);      // pair 15 (k=30,31) is pad
        wh[p] = ok ? pk2(Whh1[j * 30 + k], Whh1[j * 30 + k + 1]) : 0ull;
        wa[p] = ok ? pk2(Wih2[j * 30 + k], Wih2[j * 30 + k + 1]) : 0ull;
        wb[p] = ok ? pk2(Whh2[j * 30 + k], Whh2[j * 30 + k + 1]) : 0ull;
    }

    const float wl0 = Wlin[0 * 30 + lc], wl1 = Wlin[1 * 30 + lc];
    const float wl2 = Wlin[2 * 30 + lc], wl3 = Wlin[3 * 30 + lc];
    const float bl0 = blin[0], bl1 = blin[1], bl2 = blin[2], bl3 = blin[3];

    // ---- shared init ----
    for (int idx = tid; idx < 7 * 64; idx += NTHR) sm.hs[idx >> 6][idx & 63] = 0.0f;
    if (l == 15 && w < NB) {
        sm.xbuf[0][w] = *(const float4*)(input + ((size_t)(b0 + w) * T_SEQ + 0) * 4);
        sm.xbuf[1][w] = *(const float4*)(input + ((size_t)(b0 + w) * T_SEQ + 1) * 4);
    }
    __syncthreads();

    float c1 = 0.0f, c2 = 0.0f;    // warp w owns batch w, lane l = unit

    // helper lambda-ish macro via loop body; P-phase written inline below.

    // ---- prologue P: act1(0) from x(0), h==0 (hs zeroed) ----
    {
#pragma unroll
        for (int b = 0; b < NB; b++) {
            ulonglong2 xv = *(const ulonglong2*)&sm.xbuf[0][b];
            ull P1 = f2fma(wx0, xv.x, bias1);
            P1     = f2fma(wx1, xv.y, P1);
            float p1 = sum2(P1);
            float o1 = __shfl_xor_sync(0xffffffffu, p1, 16);
            float v  = p1 + o1;
            float a  = act_unified(v, sgate);
            if (valid && half == 0) sm.act1[b][u * 4 + g] = a;
        }
    }
    __syncthreads();
    if (w < NB && l < 30) {
        float4 A1 = *(const float4*)&sm.act1[w][l * 4];     // i,f,g,o
        c1 = A1.x * A1.z;                                    // f*0 + i*g
        sm.hs[w][l] = A1.w * tanhf_fast(c1);
    }
    __syncthreads();

    // ================= main loop: 2 barriers/step =================
#pragma unroll 1
    for (int t = 0; t < T_SEQ; t++) {
        const int nxt = (t + 1) & 1;

        // ---- P: partials for G1(t+1) and G2(t); combine via shfl; act fused ----
#pragma unroll
        for (int b = 0; b < NB; b++) {
            const ulonglong2* hp = (const ulonglong2*)sm.hs[b];
            ulonglong2 xv = *(const ulonglong2*)&sm.xbuf[nxt][b];
            ulonglong2 H0 = hp[half * 4 + 0], H1 = hp[half * 4 + 1];
            ulonglong2 H2 = hp[half * 4 + 2], H3 = hp[half * 4 + 3];
            ulonglong2 K0 = hp[8 + half * 4 + 0], K1 = hp[8 + half * 4 + 1];
            ulonglong2 K2 = hp[8 + half * 4 + 2], K3 = hp[8 + half * 4 + 3];

            ull P1 = f2fma(wx0, xv.x, bias1);
            P1     = f2fma(wx1, xv.y, P1);
            P1 = f2fma(wh[0], H0.x, P1); P1 = f2fma(wh[1], H0.y, P1);
            P1 = f2fma(wh[2], H1.x, P1); P1 = f2fma(wh[3], H1.y, P1);
            P1 = f2fma(wh[4], H2.x, P1); P1 = f2fma(wh[5], H2.y, P1);
            P1 = f2fma(wh[6], H3.x, P1); P1 = f2fma(wh[7], H3.y, P1);

            ull P2a = f2fma(wa[0], H0.x, bias2);
            P2a = f2fma(wa[1], H0.y, P2a);
            P2a = f2fma(wa[2], H1.x, P2a); P2a = f2fma(wa[3], H1.y, P2a);
            P2a = f2fma(wa[4], H2.x, P2a); P2a = f2fma(wa[5], H2.y, P2a);
            P2a = f2fma(wa[6], H3.x, P2a); P2a = f2fma(wa[7], H3.y, P2a);

            ull P2b = 0;
            P2b = f2fma(wb[0], K0.x, P2b); P2b = f2fma(wb[1], K0.y, P2b);
            P2b = f2fma(wb[2], K1.x, P2b); P2b = f2fma(wb[3], K1.y, P2b);
            P2b = f2fma(wb[4], K2.x, P2b); P2b = f2fma(wb[5], K2.y, P2b);
            P2b = f2fma(wb[6], K3.x, P2b); P2b = f2fma(wb[7], K3.y, P2b);

            float p1 = sum2(P1);
            float p2 = sum2(f2add(P2a, P2b));
            float o1 = __shfl_xor_sync(0xffffffffu, p1, 16);
            float o2 = __shfl_xor_sync(0xffffffffu, p2, 16);
            float v  = half ? (p2 + o2) : (p1 + o1);
            float a  = act_unified(v, sgate);
            if (valid) {
                float* dst = half ? &sm.act2[b][0] : &sm.act1[b][0];
                dst[u * 4 + g] = a;
            }
        }
        // x prefetch by spare lanes (r == 15, half 0)
        if (l == 15 && w < NB && t + 2 < T_SEQ)
            sm.xbuf[t & 1][w] =
                *(const float4*)(input + ((size_t)(b0 + w) * T_SEQ + (t + 2)) * 4);
        __syncthreads();

        // ---- A: c2/h2 + LIN(t); c1/h1(t+1). warp w = batch w ----
        if (w < NB) {
            const int b = w;
            float h2v = 0.0f;
            if (l < 30) {
                float4 A2 = *(const float4*)&sm.act2[b][l * 4];   // i,f,g,o
                c2  = A2.y * c2 + A2.x * A2.z;
                h2v = A2.w * tanhf_fast(c2);
                sm.hs[b][32 + l] = h2v;

                float4 A1 = *(const float4*)&sm.act1[b][l * 4];
                c1 = A1.y * c1 + A1.x * A1.z;
                sm.hs[b][l] = A1.w * tanhf_fast(c1);
            }
            float p0 = h2v * wl0, p1 = h2v * wl1, p2 = h2v * wl2, p3 = h2v * wl3;
#pragma unroll
            for (int m = 16; m >= 1; m >>= 1) {
                p0 += __shfl_xor_sync(0xffffffffu, p0, m);
                p1 += __shfl_xor_sync(0xffffffffu, p1, m);
                p2 += __shfl_xor_sync(0xffffffffu, p2, m);
                p3 += __shfl_xor_sync(0xffffffffu, p3, m);
            }
            if (l == 0) {
                float4 o4 = make_float4(p0 + bl0, p1 + bl1, p2 + bl2, p3 + bl3);
                *(float4*)(out + ((size_t)(b0 + b) * T_SEQ + t) * 4) = o4;
            }
        }
        __syncthreads();
        // t = T_SEQ-1 computes act1/h1 for step T_SEQ from stale x — finite,
        // never consumed.
    }
}

__global__ void __launch_bounds__(NTHR, 2)
lstm2_kernel(const float* __restrict__ input,
             const float* __restrict__ Wih1, const float* __restrict__ bih1,
             const float* __restrict__ Whh1, const float* __restrict__ bhh1,
             const float* __restrict__ Wih2, const float* __restrict__ bih2,
             const float* __restrict__ Whh2, const float* __restrict__ bhh2,
             const float* __restrict__ Wlin, const float* __restrict__ blin,
             float* __restrict__ out)
{
    __shared__ SMem sm;
    // 296 CTAs = 2/SM; bids s and s+148 co-locate. Per-SM nb {7,7} (s<124)
    // or {7,6}: 124*14 + 24*13 = 2048.
    const int s = blockIdx.x % 148, wq = blockIdx.x / 148;
    int nb, b0;
    if (s < 124) { b0 = s * 14 + wq * 7;                    nb = 7; }
    else         { b0 = 1736 + (s - 124) * 13 + wq * 7;     nb = (wq == 0) ? 7 : 6; }

    if (nb == 7)
        run_body<7>(input, Wih1, bih1, Whh1, bhh1, Wih2, bih2, Whh2, bhh2,
                    Wlin, blin, out, sm, b0);
    else
        run_body<6>(input, Wih1, bih1, Whh1, bhh1, Wih2, bih2, Whh2, bhh2,
                    Wlin, blin, out, sm, b0);
}

extern "C" void kernel_launch(void* const* d_in, const int* in_sizes, int n_in,
                              void* d_out, int out_size)
{
    const float* input = (const float*)d_in[0];
    const float* Wih1  = (const float*)d_in[1];
    const float* bih1  = (const float*)d_in[2];
    const float* Whh1  = (const float*)d_in[3];
    const float* bhh1  = (const float*)d_in[4];
    const float* Wih2  = (const float*)d_in[5];
    const float* bih2  = (const float*)d_in[6];
    const float* Whh2  = (const float*)d_in[7];
    const float* bhh2  = (const float*)d_in[8];
    const float* Wlin  = (const float*)d_in[9];
    const float* blin  = (const float*)d_in[10];
    float* out = (float*)d_out;

    lstm2_kernel<<<296, NTHR>>>(input, Wih1, bih1, Whh1, bhh1,
                                Wih2, bih2, Whh2, bhh2, Wlin, blin, out);
}